// round 9
// baseline (speedup 1.0000x reference)
#include <cuda_runtime.h>
#include <cuda_fp16.h>
#include <cstdint>
#include <cstddef>

// MultiAgentSEPSNetwork: 8 agents x (4096,256)->1024->1024->512 MLP,
// per-agent net via seps_idx (int32 &3).
//
// Round 9: single-term fp16 GEMM (error budget spent at rel_err 5.1e-4);
// mainloop restructured to a 3-stage cp.async pipeline with ONE
// __syncthreads per K-tile (was 2). Buffers: compute ti%3, in-flight
// (ti+1)%3, fill (ti+2)%3 -- disjoint; the top-of-loop barrier protects
// (ti+2)%3 == (ti-1)%3 reuse. Dynamic smem (60KB) since >48KB static.

namespace seps {

constexpr int NA = 8;
constexpr int NE = 4096;

// ---- persistent device scratch ----
__device__ uint32_t g_xh [(size_t)NA * NE * 128];    // x fp16 [M][K2] words
__device__ uint32_t g_w1h[(size_t)4 * 1024 * 128];   // W^T fp16 [S][N][K2]
__device__ uint32_t g_w2h[(size_t)4 * 1024 * 512];
__device__ uint32_t g_w3h[(size_t)4 * 512 * 512];
__device__ uint32_t g_h1h[(size_t)NA * NE * 512];    // h fp16 [M][K2]
__device__ uint32_t g_h2h[(size_t)NA * NE * 512];

__device__ __forceinline__ uint32_t smem_u32(const void* p) {
    uint32_t a;
    asm("{ .reg .u64 t; cvta.to.shared.u64 t, %1; cvt.u32.u64 %0, t; }" : "=r"(a) : "l"(p));
    return a;
}
__device__ __forceinline__ uint32_t pack2h(float v0, float v1) {
    __half h0 = __float2half_rn(v0), h1 = __float2half_rn(v1);
    return (uint32_t)__half_as_ushort(h0) | ((uint32_t)__half_as_ushort(h1) << 16);
}
__device__ __forceinline__ void cp_async16(uint32_t dst, const void* src) {
    asm volatile("cp.async.cg.shared.global [%0], [%1], 16;" :: "r"(dst), "l"(src));
}
__device__ __forceinline__ void cp_commit() { asm volatile("cp.async.commit_group;"); }
template<int N> __device__ __forceinline__ void cp_wait() {
    asm volatile("cp.async.wait_group %0;" :: "n"(N));
}
__device__ __forceinline__ void mma_f16(float* c, const uint32_t* a, const uint32_t* b) {
    asm volatile(
        "mma.sync.aligned.m16n8k16.row.col.f32.f16.f16.f32 "
        "{%0,%1,%2,%3}, {%4,%5,%6,%7}, {%8,%9}, {%0,%1,%2,%3};"
        : "+f"(c[0]), "+f"(c[1]), "+f"(c[2]), "+f"(c[3])
        : "r"(a[0]), "r"(a[1]), "r"(a[2]), "r"(a[3]),
          "r"(b[0]), "r"(b[1]));
}
__device__ __forceinline__ void ldsm_x4(uint32_t& r0, uint32_t& r1, uint32_t& r2,
                                        uint32_t& r3, uint32_t addr) {
    asm volatile("ldmatrix.sync.aligned.m8n8.x4.shared.b16 {%0,%1,%2,%3}, [%4];"
                 : "=r"(r0), "=r"(r1), "=r"(r2), "=r"(r3) : "r"(addr));
}

// ---- prepass ----
__global__ void pack_act(const float2* __restrict__ in, uint32_t* __restrict__ hi, int n) {
    int i = blockIdx.x * blockDim.x + threadIdx.x;
    if (i < n) { float2 v = in[i]; hi[i] = pack2h(v.x, v.y); }
}
// W [S,K,N] f32 -> transposed fp16 plane [S,N,K2]; word = {k=2kw, k=2kw+1}.
__global__ void pack_wgt_t(const float* __restrict__ in,
                           uint32_t* __restrict__ hi, int K2, int N, int total) {
    int i = blockIdx.x * blockDim.x + threadIdx.x;
    if (i >= total) return;
    int kw = i % K2;
    int n  = (i / K2) % N;
    int s  = i / (K2 * N);
    const float* base = in + ((size_t)s * (2 * K2) + 2 * kw) * N + n;
    hi[i] = pack2h(base[0], base[N]);
}

// ---- GEMM: CTA 128x128, KT=32, 8 warps each 32x64, 3-stage cp.async ----
template<int K, int NOUT, bool RELU, bool PACK_OUT>
__global__ __launch_bounds__(256, 2)
void gemm_f16(const uint32_t* __restrict__ Ah, const uint32_t* __restrict__ Bh,
              const float* __restrict__ bias, const int* __restrict__ sidx,
              float* __restrict__ Yf, uint32_t* __restrict__ Yh)
{
    constexpr int KT = 32;
    constexpr int KW = KT / 2;
    constexpr int ST = 20;                     // smem row stride (words)
    constexpr int NT = K / KT;
    constexpr int K2 = K / 2;
    constexpr int BUFW = 128 * ST;             // words per operand buffer
    constexpr uint32_t STAGE_B = 2 * BUFW * 4; // bytes per stage (A+B)

    extern __shared__ uint32_t dsm[];          // 3 stages x (A | B)

    const int tid  = threadIdx.x;
    const int lane = tid & 31;
    const int warp = tid >> 5;
    const int g = lane >> 2;
    const int t = lane & 3;
    const int wm = (warp & 3) * 32;
    const int wn = (warp >> 2) * 64;

    const int agent = blockIdx.z;
    const int m0 = blockIdx.y * 128;
    const int n0 = blockIdx.x * 128;
    const int s = sidx[agent] & 3;

    const uint32_t* Aha = Ah + (size_t)agent * NE * K2;
    const uint32_t* Bhs = Bh + (size_t)s * NOUT * K2;
    const float*    bs  = bias + (size_t)s * NOUT;

    const uint32_t base = smem_u32(dsm);

    float acc[2][8][4];
    #pragma unroll
    for (int mi = 0; mi < 2; ++mi)
        #pragma unroll
        for (int ni = 0; ni < 8; ++ni)
            #pragma unroll
            for (int j = 0; j < 4; ++j) acc[mi][ni][j] = 0.f;

    auto issue = [&](int ti, int buf) {
        const int kw0 = ti * KW;
        const uint32_t aB = base + (uint32_t)buf * STAGE_B;
        const uint32_t bB = aB + BUFW * 4;
        #pragma unroll
        for (int p = 0; p < 2; ++p) {
            const int idx = p * 256 + tid;          // 0..511
            const int row = idx >> 2;
            const int kg  = (idx & 3) * 4;
            const uint32_t so = (uint32_t)(row * ST + kg) * 4;
            cp_async16(aB + so, Aha + (size_t)(m0 + row) * K2 + kw0 + kg);
            cp_async16(bB + so, Bhs + (size_t)(n0 + row) * K2 + kw0 + kg);
        }
        cp_commit();
    };

    issue(0, 0);
    issue(1, 1);

    const uint32_t a_row = (uint32_t)(wm + (lane & 15));
    const uint32_t a_kw  = (uint32_t)((lane >> 4) << 2);
    const uint32_t b_row = (uint32_t)(wn + ((lane >> 4) << 3) + (lane & 7));
    const uint32_t b_kw  = (uint32_t)(((lane >> 3) & 1) << 2);

    #pragma unroll 1
    for (int ti = 0; ti < NT; ++ti) {
        if (ti + 1 < NT) cp_wait<1>(); else cp_wait<0>();
        __syncthreads();                       // single barrier per tile
        if (ti + 2 < NT) issue(ti + 2, (ti + 2) % 3);

        const uint32_t aB = base + (uint32_t)(ti % 3) * STAGE_B;
        const uint32_t bB = aB + BUFW * 4;

        #pragma unroll
        for (int ks = 0; ks < 2; ++ks) {
            const uint32_t kso = (uint32_t)(ks * 8);
            uint32_t fA[2][4];
            #pragma unroll
            for (int mi = 0; mi < 2; ++mi) {
                const uint32_t off = ((a_row + mi * 16) * ST + kso + a_kw) * 4;
                ldsm_x4(fA[mi][0], fA[mi][1], fA[mi][2], fA[mi][3], aB + off);
            }
            uint32_t fB[8][2];
            #pragma unroll
            for (int np = 0; np < 4; ++np) {
                const uint32_t off = ((b_row + np * 16) * ST + kso + b_kw) * 4;
                ldsm_x4(fB[2*np][0], fB[2*np][1], fB[2*np+1][0], fB[2*np+1][1], bB + off);
            }
            #pragma unroll
            for (int ni = 0; ni < 8; ++ni)
                #pragma unroll
                for (int mi = 0; mi < 2; ++mi)
                    mma_f16(acc[mi][ni], fA[mi], fB[ni]);
        }
    }

    // ---- epilogue ----
    float*    Yfa = PACK_OUT ? nullptr : (Yf + (size_t)agent * NE * NOUT);
    uint32_t* Yha = PACK_OUT ? (Yh + (size_t)agent * NE * (NOUT / 2)) : nullptr;

    #pragma unroll
    for (int mi = 0; mi < 2; ++mi) {
        const int r = m0 + wm + mi * 16 + g;
        #pragma unroll
        for (int ni = 0; ni < 8; ++ni) {
            const int ccol = n0 + wn + ni * 8 + 2 * t;
            const float2 bb = *reinterpret_cast<const float2*>(bs + ccol);
            float v0 = acc[mi][ni][0] + bb.x;
            float v1 = acc[mi][ni][1] + bb.y;
            float v2 = acc[mi][ni][2] + bb.x;
            float v3 = acc[mi][ni][3] + bb.y;
            if (RELU) {
                v0 = fmaxf(v0, 0.f); v1 = fmaxf(v1, 0.f);
                v2 = fmaxf(v2, 0.f); v3 = fmaxf(v3, 0.f);
            }
            if (PACK_OUT) {
                Yha[(size_t)(r    ) * (NOUT / 2) + ccol / 2] = pack2h(v0, v1);
                Yha[(size_t)(r + 8) * (NOUT / 2) + ccol / 2] = pack2h(v2, v3);
            } else {
                *reinterpret_cast<float2*>(Yfa + (size_t)(r    ) * NOUT + ccol) = make_float2(v0, v1);
                *reinterpret_cast<float2*>(Yfa + (size_t)(r + 8) * NOUT + ccol) = make_float2(v2, v3);
            }
        }
    }
}

} // namespace seps

extern "C" void kernel_launch(void* const* d_in, const int* in_sizes, int n_in,
                              void* d_out, int out_size)
{
    using namespace seps;
    const float* x   = (const float*)d_in[0];
    const float* W1  = (const float*)d_in[1];
    const float* b1  = (const float*)d_in[2];
    const float* W2  = (const float*)d_in[3];
    const float* b2  = (const float*)d_in[4];
    const float* W3  = (const float*)d_in[5];
    const float* b3  = (const float*)d_in[6];
    const int* sidx  = (const int*)d_in[7];
    float* out = (float*)d_out;

    uint32_t *xh, *w1h, *w2h, *w3h, *h1h, *h2h;
    cudaGetSymbolAddress((void**)&xh,  g_xh);
    cudaGetSymbolAddress((void**)&w1h, g_w1h);
    cudaGetSymbolAddress((void**)&w2h, g_w2h);
    cudaGetSymbolAddress((void**)&w3h, g_w3h);
    cudaGetSymbolAddress((void**)&h1h, g_h1h);
    cudaGetSymbolAddress((void**)&h2h, g_h2h);

    // prepass
    {
        int nx = NA * NE * 128;
        pack_act<<<(nx + 255) / 256, 256>>>((const float2*)x, xh, nx);
        int n1 = 4 * 1024 * 128;
        pack_wgt_t<<<(n1 + 255) / 256, 256>>>(W1, w1h, 128, 1024, n1);
        int n2 = 4 * 1024 * 512;
        pack_wgt_t<<<(n2 + 255) / 256, 256>>>(W2, w2h, 512, 1024, n2);
        int n3 = 4 * 512 * 512;
        pack_wgt_t<<<(n3 + 255) / 256, 256>>>(W3, w3h, 512, 512, n3);
    }

    // 3 stages x (A 10240B + B 10240B) = 61440 bytes dynamic smem
    const int dyn = 3 * 2 * 128 * 20 * 4;
    cudaFuncSetAttribute(gemm_f16< 256, 1024, true,  true >,
                         cudaFuncAttributeMaxDynamicSharedMemorySize, dyn);
    cudaFuncSetAttribute(gemm_f16<1024, 1024, true,  true >,
                         cudaFuncAttributeMaxDynamicSharedMemorySize, dyn);
    cudaFuncSetAttribute(gemm_f16<1024,  512, false, false>,
                         cudaFuncAttributeMaxDynamicSharedMemorySize, dyn);

    const dim3 blk(256);
    gemm_f16< 256, 1024, true,  true ><<<dim3(8, 32, 8), blk, dyn>>>(xh,  w1h, b1, sidx, nullptr, h1h);
    gemm_f16<1024, 1024, true,  true ><<<dim3(8, 32, 8), blk, dyn>>>(h1h, w2h, b2, sidx, nullptr, h2h);
    gemm_f16<1024,  512, false, false><<<dim3(4, 32, 8), blk, dyn>>>(h2h, w3h, b3, sidx, out, nullptr);
}